// round 1
// baseline (speedup 1.0000x reference)
#include <cuda_runtime.h>
#include <math.h>
#include <math_constants.h>

#define Bn 4
#define Tn 1024
#define En 1024
#define Hn 16
#define Dn 64
#define Mn (Bn*Tn)        // 4096 rows
#define BHn (Bn*Hn)       // 64

// ---------------- device scratch (no cudaMalloc allowed) ----------------
__device__ float g_q[Bn*Hn*Tn*Dn];   // [B,H,T,D]
__device__ float g_k[Bn*Hn*Tn*Dn];
__device__ float g_v[Bn*Hn*Tn*Dn];
__device__ float g_o[Bn*Tn*En];      // [B,T,E] (E = h*D+d)
__device__ float g_Tmean;
__device__ float g_keepScale;

// ---------------- prep: Tmean from theta ----------------
__global__ void prep_kernel(const float* __restrict__ theta) {
    if (threadIdx.x == 0) {
        double acc = 0.0;
        for (int h = 0; h < Hn; h++) {
            double th = 1.0 / (1.0 + exp(-(double)theta[h])) * (CUDART_PI / 2.0);
            acc += fabs(sin(2.0 * th));
        }
        float tm = (float)(acc / (double)Hn);
        g_Tmean = tm;
        g_keepScale = 1.0f / (1.0f - tm + 1e-8f);
    }
}

// ---------------- QKV projection: C = x @ W^T + b, 128x128x8 SGEMM ----------------
// grid.x = 3072/128 = 24 (N over [Wq|Wk|Wv]), grid.y = 4096/128 = 32 (M)
__global__ __launch_bounds__(256) void qkv_kernel(
    const float* __restrict__ x,
    const float* __restrict__ Wq, const float* __restrict__ bq,
    const float* __restrict__ Wk, const float* __restrict__ bk,
    const float* __restrict__ Wv, const float* __restrict__ bv)
{
    __shared__ float As[8][128];
    __shared__ float Bs[8][128];

    const int tid = threadIdx.x;
    const int n0 = blockIdx.x * 128;
    const int m0 = blockIdx.y * 128;
    const int which = n0 >> 10;               // 0=q 1=k 2=v (128 | 1024)
    const int nloc0 = n0 & 1023;

    const float* W    = (which == 0) ? Wq : (which == 1) ? Wk : Wv;
    const float* bias = (which == 0) ? bq : (which == 1) ? bk : bv;
    float* out        = (which == 0) ? g_q : (which == 1) ? g_k : g_v;

    const int lrow   = tid >> 1;              // 0..127
    const int lchunk = (tid & 1) * 4;         // 0 or 4
    const float* Aptr = x + (size_t)(m0 + lrow) * En + lchunk;
    const float* Bptr = W + (size_t)(nloc0 + lrow) * En + lchunk;

    const int ty = tid >> 4, tx = tid & 15;

    float c[8][8];
#pragma unroll
    for (int i = 0; i < 8; i++)
#pragma unroll
        for (int j = 0; j < 8; j++) c[i][j] = 0.f;

    for (int kb = 0; kb < En; kb += 8) {
        float4 av  = *(const float4*)(Aptr + kb);
        float4 bv4 = *(const float4*)(Bptr + kb);
        __syncthreads();
        As[lchunk + 0][lrow] = av.x;  As[lchunk + 1][lrow] = av.y;
        As[lchunk + 2][lrow] = av.z;  As[lchunk + 3][lrow] = av.w;
        Bs[lchunk + 0][lrow] = bv4.x; Bs[lchunk + 1][lrow] = bv4.y;
        Bs[lchunk + 2][lrow] = bv4.z; Bs[lchunk + 3][lrow] = bv4.w;
        __syncthreads();
#pragma unroll
        for (int k = 0; k < 8; k++) {
            float4 a0 = *(const float4*)&As[k][ty * 8];
            float4 a1 = *(const float4*)&As[k][ty * 8 + 4];
            float4 b0 = *(const float4*)&Bs[k][tx * 8];
            float4 b1 = *(const float4*)&Bs[k][tx * 8 + 4];
            float a[8] = {a0.x, a0.y, a0.z, a0.w, a1.x, a1.y, a1.z, a1.w};
            float b[8] = {b0.x, b0.y, b0.z, b0.w, b1.x, b1.y, b1.z, b1.w};
#pragma unroll
            for (int i = 0; i < 8; i++)
#pragma unroll
                for (int j = 0; j < 8; j++) c[i][j] += a[i] * b[j];
        }
    }

    // epilogue: scatter into [B,H,T,D]
#pragma unroll
    for (int i = 0; i < 8; i++) {
        int m = m0 + ty * 8 + i;
        int b = m >> 10, t = m & 1023;
#pragma unroll
        for (int j = 0; j < 8; j++) {
            int n = nloc0 + tx * 8 + j;
            int h = n >> 6, d = n & 63;
            out[(((size_t)(b * Hn + h)) * Tn + t) * Dn + d] = c[i][j] + bias[n];
        }
    }
}

// ---------------- flash attention, fp32, 128q x 128s tiles ----------------
#define BQ 128
#define BS 128
#define PSTR 132
#define SWZ(d) ((((d) >> 2) & 7) << 2)
// dyn smem floats: QsT 64*128 | KsT 64*128 | Vs 128*64 | Ps 128*132
#define ATTN_SMEM_FLOATS (8192 + 8192 + 8192 + 128*PSTR)
#define ATTN_SMEM_BYTES  (ATTN_SMEM_FLOATS * 4)

__global__ __launch_bounds__(256, 1) void attn_kernel(const float* __restrict__ noise)
{
    extern __shared__ float sm[];
    float* QsT = sm;                 // [d][r], swizzled columns
    float* KsT = sm + 8192;          // [d][s], swizzled columns
    float* Vs  = sm + 16384;         // [s][d]
    float* Ps  = sm + 24576;         // [r][s], stride PSTR

    const int tid = threadIdx.x;
    const int bh  = blockIdx.y;
    const int q0  = blockIdx.x * BQ;
    const int ty  = tid >> 4, tx = tid & 15;

    const float* Qg = g_q + ((size_t)bh * Tn + q0) * Dn;
    const float* Kg = g_k + (size_t)bh * Tn * Dn;
    const float* Vg = g_v + (size_t)bh * Tn * Dn;
    const float* Ng = noise + (size_t)bh * Tn * Tn + (size_t)q0 * Tn;

    const float Tm    = g_Tmean;
    const float scale = 0.125f;      // D^-0.5, D=64

    // load Q tile (scaled) transposed + swizzled
    for (int idx = tid; idx < BQ * 16; idx += 256) {
        int r  = idx >> 4;
        int c4 = (idx & 15) << 2;
        int sw = SWZ(c4);
        float4 qv = *(const float4*)(Qg + (size_t)r * Dn + c4);
        QsT[(c4 + 0) * BQ + (r ^ sw)] = qv.x * scale;
        QsT[(c4 + 1) * BQ + (r ^ sw)] = qv.y * scale;
        QsT[(c4 + 2) * BQ + (r ^ sw)] = qv.z * scale;
        QsT[(c4 + 3) * BQ + (r ^ sw)] = qv.w * scale;
    }

    float m[8], l[8], acc[8][4];
#pragma unroll
    for (int i = 0; i < 8; i++) {
        m[i] = -1e30f; l[i] = 0.f;
        acc[i][0] = acc[i][1] = acc[i][2] = acc[i][3] = 0.f;
    }

    for (int st = 0; st < Tn; st += BS) {
        __syncthreads();  // guards prev-iter Ps/Vs reads and initial Q load
        // load K (transposed+swizzled) and V tiles
        for (int idx = tid; idx < BS * 16; idx += 256) {
            int r  = idx >> 4;
            int c4 = (idx & 15) << 2;
            int sw = SWZ(c4);
            float4 kv = *(const float4*)(Kg + (size_t)(st + r) * Dn + c4);
            KsT[(c4 + 0) * BS + (r ^ sw)] = kv.x;
            KsT[(c4 + 1) * BS + (r ^ sw)] = kv.y;
            KsT[(c4 + 2) * BS + (r ^ sw)] = kv.z;
            KsT[(c4 + 3) * BS + (r ^ sw)] = kv.w;
            float4 vv = *(const float4*)(Vg + (size_t)(st + r) * Dn + c4);
            *(float4*)&Vs[r * Dn + c4] = vv;
        }
        __syncthreads();

        // S = (Q*scale) @ K^T  (8x8 per thread)
        float sreg[8][8];
#pragma unroll
        for (int i = 0; i < 8; i++)
#pragma unroll
            for (int j = 0; j < 8; j++) sreg[i][j] = 0.f;

#pragma unroll 4
        for (int d = 0; d < Dn; d++) {
            int sw = SWZ(d);
            const float* qrow = &QsT[d * BQ];
            const float* krow = &KsT[d * BS];
            float4 a0 = *(const float4*)(qrow + ((ty * 8) ^ sw));
            float4 a1 = *(const float4*)(qrow + (((ty * 8) ^ sw) ^ 4));
            float4 b0 = *(const float4*)(krow + ((tx * 8) ^ sw));
            float4 b1 = *(const float4*)(krow + (((tx * 8) ^ sw) ^ 4));
            float a[8] = {a0.x, a0.y, a0.z, a0.w, a1.x, a1.y, a1.z, a1.w};
            float b[8] = {b0.x, b0.y, b0.z, b0.w, b1.x, b1.y, b1.z, b1.w};
#pragma unroll
            for (int i = 0; i < 8; i++)
#pragma unroll
                for (int j = 0; j < 8; j++) sreg[i][j] += a[i] * b[j];
        }

        // online softmax: m/l track UN-masked exp sums; mask goes on numerator
#pragma unroll
        for (int i = 0; i < 8; i++) {
            float tmax = sreg[i][0];
#pragma unroll
            for (int j = 1; j < 8; j++) tmax = fmaxf(tmax, sreg[i][j]);
            tmax = fmaxf(tmax, __shfl_xor_sync(0xffffffffu, tmax, 1, 16));
            tmax = fmaxf(tmax, __shfl_xor_sync(0xffffffffu, tmax, 2, 16));
            tmax = fmaxf(tmax, __shfl_xor_sync(0xffffffffu, tmax, 4, 16));
            tmax = fmaxf(tmax, __shfl_xor_sync(0xffffffffu, tmax, 8, 16));
            float mn    = fmaxf(m[i], tmax);
            float alpha = __expf(m[i] - mn);
            m[i] = mn;
            float rs = 0.f;
#pragma unroll
            for (int j = 0; j < 8; j++) { sreg[i][j] = __expf(sreg[i][j] - mn); rs += sreg[i][j]; }
            rs += __shfl_xor_sync(0xffffffffu, rs, 1, 16);
            rs += __shfl_xor_sync(0xffffffffu, rs, 2, 16);
            rs += __shfl_xor_sync(0xffffffffu, rs, 4, 16);
            rs += __shfl_xor_sync(0xffffffffu, rs, 8, 16);
            l[i] = l[i] * alpha + rs;
            acc[i][0] *= alpha; acc[i][1] *= alpha; acc[i][2] *= alpha; acc[i][3] *= alpha;
        }

        // apply keep mask from noise, stage P into shared
#pragma unroll
        for (int i = 0; i < 8; i++) {
            const float* nrow = Ng + (size_t)(ty * 8 + i) * Tn + st + tx * 8;
            float4 n0 = *(const float4*)nrow;
            float4 n1 = *(const float4*)(nrow + 4);
            float p0 = (n0.x > Tm) ? sreg[i][0] : 0.f;
            float p1 = (n0.y > Tm) ? sreg[i][1] : 0.f;
            float p2 = (n0.z > Tm) ? sreg[i][2] : 0.f;
            float p3 = (n0.w > Tm) ? sreg[i][3] : 0.f;
            float p4 = (n1.x > Tm) ? sreg[i][4] : 0.f;
            float p5 = (n1.y > Tm) ? sreg[i][5] : 0.f;
            float p6 = (n1.z > Tm) ? sreg[i][6] : 0.f;
            float p7 = (n1.w > Tm) ? sreg[i][7] : 0.f;
            *(float4*)&Ps[(ty * 8 + i) * PSTR + tx * 8]     = make_float4(p0, p1, p2, p3);
            *(float4*)&Ps[(ty * 8 + i) * PSTR + tx * 8 + 4] = make_float4(p4, p5, p6, p7);
        }
        __syncthreads();

        // acc += P_keep @ V
#pragma unroll 2
        for (int ss = 0; ss < BS; ss++) {
            float4 bv = *(const float4*)&Vs[ss * Dn + tx * 4];
#pragma unroll
            for (int i = 0; i < 8; i++) {
                float a = Ps[(ty * 8 + i) * PSTR + ss];
                acc[i][0] += a * bv.x; acc[i][1] += a * bv.y;
                acc[i][2] += a * bv.z; acc[i][3] += a * bv.w;
            }
        }
    }

    // epilogue: out = acc / l * keepScale -> g_o[b, t, h*D+d]
    const float ks = g_keepScale;
    const int b = bh >> 4, h = bh & 15;
#pragma unroll
    for (int i = 0; i < 8; i++) {
        float inv = ks / l[i];
        int r = q0 + ty * 8 + i;
        float4 o;
        o.x = acc[i][0] * inv; o.y = acc[i][1] * inv;
        o.z = acc[i][2] * inv; o.w = acc[i][3] * inv;
        *(float4*)&g_o[((size_t)(b * Tn + r)) * En + h * Dn + tx * 4] = o;
    }
}

// ---------------- output projection: out = g_o @ Wo^T + bo ----------------
// grid.x = 1024/128 = 8, grid.y = 4096/128 = 32
__global__ __launch_bounds__(256) void oproj_kernel(
    const float* __restrict__ Wo, const float* __restrict__ bo,
    float* __restrict__ out)
{
    __shared__ float As[8][128];
    __shared__ float Bs[8][128];

    const int tid = threadIdx.x;
    const int n0 = blockIdx.x * 128;
    const int m0 = blockIdx.y * 128;

    const int lrow   = tid >> 1;
    const int lchunk = (tid & 1) * 4;
    const float* Aptr = g_o + (size_t)(m0 + lrow) * En + lchunk;
    const float* Bptr = Wo  + (size_t)(n0 + lrow) * En + lchunk;

    const int ty = tid >> 4, tx = tid & 15;

    float c[8][8];
#pragma unroll
    for (int i = 0; i < 8; i++)
#pragma unroll
        for (int j = 0; j < 8; j++) c[i][j] = 0.f;

    for (int kb = 0; kb < En; kb += 8) {
        float4 av  = *(const float4*)(Aptr + kb);
        float4 bv4 = *(const float4*)(Bptr + kb);
        __syncthreads();
        As[lchunk + 0][lrow] = av.x;  As[lchunk + 1][lrow] = av.y;
        As[lchunk + 2][lrow] = av.z;  As[lchunk + 3][lrow] = av.w;
        Bs[lchunk + 0][lrow] = bv4.x; Bs[lchunk + 1][lrow] = bv4.y;
        Bs[lchunk + 2][lrow] = bv4.z; Bs[lchunk + 3][lrow] = bv4.w;
        __syncthreads();
#pragma unroll
        for (int k = 0; k < 8; k++) {
            float4 a0 = *(const float4*)&As[k][ty * 8];
            float4 a1 = *(const float4*)&As[k][ty * 8 + 4];
            float4 b0 = *(const float4*)&Bs[k][tx * 8];
            float4 b1 = *(const float4*)&Bs[k][tx * 8 + 4];
            float a[8] = {a0.x, a0.y, a0.z, a0.w, a1.x, a1.y, a1.z, a1.w};
            float b[8] = {b0.x, b0.y, b0.z, b0.w, b1.x, b1.y, b1.z, b1.w};
#pragma unroll
            for (int i = 0; i < 8; i++)
#pragma unroll
                for (int j = 0; j < 8; j++) c[i][j] += a[i] * b[j];
        }
    }

#pragma unroll
    for (int i = 0; i < 8; i++) {
        int msel = m0 + ty * 8 + i;
#pragma unroll
        for (int j = 0; j < 8; j++) {
            int n = n0 + tx * 8 + j;
            out[(size_t)msel * En + n] = c[i][j] + bo[n];
        }
    }
}

// ---------------- launch ----------------
extern "C" void kernel_launch(void* const* d_in, const int* in_sizes, int n_in,
                              void* d_out, int out_size)
{
    const float* x     = (const float*)d_in[0];
    const float* noise = (const float*)d_in[1];
    const float* Wq    = (const float*)d_in[2];
    const float* bq    = (const float*)d_in[3];
    const float* Wk    = (const float*)d_in[4];
    const float* bk    = (const float*)d_in[5];
    const float* Wv    = (const float*)d_in[6];
    const float* bv    = (const float*)d_in[7];
    const float* Wo    = (const float*)d_in[8];
    const float* bo    = (const float*)d_in[9];
    const float* theta = (const float*)d_in[10];
    // d_in[11] = corr_w: per-head bias is constant along the softmax axis -> exactly cancels.
    float* out = (float*)d_out;

    cudaFuncSetAttribute(attn_kernel, cudaFuncAttributeMaxDynamicSharedMemorySize,
                         ATTN_SMEM_BYTES);

    prep_kernel<<<1, 32>>>(theta);
    qkv_kernel<<<dim3(24, 32), 256>>>(x, Wq, bq, Wk, bk, Wv, bv);
    attn_kernel<<<dim3(Tn / BQ, BHn), 256, ATTN_SMEM_BYTES>>>(noise);
    oproj_kernel<<<dim3(8, 32), 256>>>(Wo, bo, out);
}

// round 7
// speedup vs baseline: 1.5853x; 1.5853x over previous
#include <cuda_runtime.h>
#include <cuda_bf16.h>
#include <math.h>
#include <math_constants.h>
#include <cstdint>

#define Bn 4
#define Tn 1024
#define En 1024
#define Hn 16
#define Dn 64
#define Mn (Bn*Tn)        // 4096 rows
#define BHn (Bn*Hn)       // 64

// ---------------- device scratch ----------------
__device__ float g_q[Bn*Hn*Tn*Dn];   // [B,H,T,D] fp32
__device__ float g_k[Bn*Hn*Tn*Dn];
__device__ float g_v[Bn*Hn*Tn*Dn];
__device__ __nv_bfloat16 g_xh[Mn*En], g_xl[Mn*En];       // x split
__device__ __nv_bfloat16 g_wh[4096*En], g_wl[4096*En];   // [Wq|Wk|Wv|Wo] split
__device__ __nv_bfloat16 g_oh[Mn*En], g_ol[Mn*En];       // attn out split
__device__ float g_Tmean;
__device__ float g_keepScale;

// single extern dynamic-smem symbol for the whole TU
extern __shared__ char dsm[];

// ---------------- PTX helpers (base-target-safe only) ----------------
__device__ __forceinline__ uint32_t smem_u32(const void* p) {
    uint32_t a;
    asm("{ .reg .u64 t; cvta.to.shared.u64 t, %1; cvt.u32.u64 %0, t; }" : "=r"(a) : "l"(p));
    return a;
}
__device__ __forceinline__ void ldsm_x4(uint32_t& r0, uint32_t& r1, uint32_t& r2, uint32_t& r3,
                                        uint32_t addr) {
    asm volatile("ldmatrix.sync.aligned.m8n8.x4.shared.b16 {%0,%1,%2,%3}, [%4];"
        : "=r"(r0), "=r"(r1), "=r"(r2), "=r"(r3) : "r"(addr));
}
__device__ __forceinline__ void ldsm_x2(uint32_t& r0, uint32_t& r1, uint32_t addr) {
    asm volatile("ldmatrix.sync.aligned.m8n8.x2.shared.b16 {%0,%1}, [%2];"
        : "=r"(r0), "=r"(r1) : "r"(addr));
}
__device__ __forceinline__ void mma_bf16(float* d, uint32_t a0, uint32_t a1, uint32_t a2,
                                         uint32_t a3, uint32_t b0, uint32_t b1) {
    asm volatile("mma.sync.aligned.m16n8k16.row.col.f32.bf16.bf16.f32 "
        "{%0,%1,%2,%3}, {%4,%5,%6,%7}, {%8,%9}, {%0,%1,%2,%3};"
        : "+f"(d[0]), "+f"(d[1]), "+f"(d[2]), "+f"(d[3])
        : "r"(a0), "r"(a1), "r"(a2), "r"(a3), "r"(b0), "r"(b1));
}

// ---------------- prep: Tmean from theta ----------------
__global__ void prep_kernel(const float* __restrict__ theta) {
    if (threadIdx.x == 0) {
        double acc = 0.0;
        for (int h = 0; h < Hn; h++) {
            double th = 1.0 / (1.0 + exp(-(double)theta[h])) * (CUDART_PI / 2.0);
            acc += fabs(sin(2.0 * th));
        }
        float tm = (float)(acc / (double)Hn);
        g_Tmean = tm;
        g_keepScale = 1.0f / (1.0f - tm + 1e-8f);
    }
}

// ---------------- fp32 -> bf16 hi/lo split ----------------
// dst_sel: 0 -> g_xh/g_xl, 1 -> g_wh/g_wl (at element offset dst_off)
__global__ __launch_bounds__(256) void conv_kernel(const float* __restrict__ src,
                                                   int dst_sel, size_t dst_off, int n4) {
    int i = blockIdx.x * 256 + threadIdx.x;
    if (i >= n4) return;
    __nv_bfloat16* dh = (dst_sel == 0) ? g_xh : g_wh;
    __nv_bfloat16* dl = (dst_sel == 0) ? g_xl : g_wl;
    dh += dst_off; dl += dst_off;
    float4 v = ((const float4*)src)[i];
    __nv_bfloat16 h0 = __float2bfloat16(v.x), h1 = __float2bfloat16(v.y);
    __nv_bfloat16 h2 = __float2bfloat16(v.z), h3 = __float2bfloat16(v.w);
    __nv_bfloat16 l0 = __float2bfloat16(v.x - __bfloat162float(h0));
    __nv_bfloat16 l1 = __float2bfloat16(v.y - __bfloat162float(h1));
    __nv_bfloat16 l2 = __float2bfloat16(v.z - __bfloat162float(h2));
    __nv_bfloat16 l3 = __float2bfloat16(v.w - __bfloat162float(h3));
    ((__nv_bfloat162*)dh)[2*i]   = __halves2bfloat162(h0, h1);
    ((__nv_bfloat162*)dh)[2*i+1] = __halves2bfloat162(h2, h3);
    ((__nv_bfloat162*)dl)[2*i]   = __halves2bfloat162(l0, l1);
    ((__nv_bfloat162*)dl)[2*i+1] = __halves2bfloat162(l2, l3);
}

// ---------------- HMMA split-bf16 GEMM: C[128,128] = A @ B^T (+bias) ----------------
// a_sel: 0 = x split (g_xh/g_xl), 1 = attn-out split (g_oh/g_ol)
// mode 0: qkv scatter (bias_q/k/v), mode 1: oproj -> out (bias_q slot = bo)
// smem: 4 tiles [128][GP] bf16 (Ah, Al, Bh, Bl), GP=40 pitch (bank-conflict-free LDSM)
#define GP 40
#define GTILE_E (128 * GP)                  // elems per tile
#define GEMM_SMEM_BYTES (4 * GTILE_E * 2)   // 40960

__global__ __launch_bounds__(256, 2) void hmma_linear_kernel(
    int a_sel, int b_row0,
    const float* __restrict__ bias_q, const float* __restrict__ bias_k,
    const float* __restrict__ bias_v,
    float* __restrict__ out, int mode)
{
    __nv_bfloat16* Ahs = (__nv_bfloat16*)dsm;
    __nv_bfloat16* Als = Ahs + GTILE_E;
    __nv_bfloat16* Bhs = Ahs + 2 * GTILE_E;
    __nv_bfloat16* Bls = Ahs + 3 * GTILE_E;

    const int tid  = threadIdx.x;
    const int wid  = tid >> 5, lane = tid & 31;
    const int n0g  = blockIdx.x * 128;
    const int m0   = blockIdx.y * 128;
    const int wM   = (wid & 3) * 32;     // warp m-band (4 bands of 32)
    const int wN   = (wid >> 2) * 64;    // warp n-band (2 bands of 64)

    const __nv_bfloat16* Ahp = ((a_sel == 0) ? g_xh : g_oh) + (size_t)m0 * En;
    const __nv_bfloat16* Alp = ((a_sel == 0) ? g_xl : g_ol) + (size_t)m0 * En;
    const __nv_bfloat16* Bhp = g_wh + (size_t)(b_row0 + n0g) * En;
    const __nv_bfloat16* Blp = g_wl + (size_t)(b_row0 + n0g) * En;

    float acc[2][8][4];
#pragma unroll
    for (int i = 0; i < 2; i++)
#pragma unroll
        for (int j = 0; j < 8; j++)
#pragma unroll
            for (int q = 0; q < 4; q++) acc[i][j][q] = 0.f;

    // per-thread gmem/smem copy coords: 2 threads per row, 2 x 16B each
    const int cr = tid >> 1;              // row 0..127
    const int cj0 = (tid & 1) * 2;        // 16B-chunk index 0..3 (2 chunks)

    // ldmatrix addresses (fixed per thread, varying k offset added later)
    const int arow = (lane & 7) | (((lane >> 3) & 1) << 3);     // 0..15
    const int akoff = ((lane >> 4) & 1) * 8;                    // 0 or 8 elems
    const int brow = lane & 15 >= 8 ? 0 : 0;                    // placeholder (unused)
    const int bln  = lane & 7;                                  // B n-row within frag
    const int bkoff = ((lane >> 3) & 1) * 8;                    // 0/8 for lanes 0-15; lanes 16+ replicate
    const int blnr = (lane & 15) & 7;

    for (int c = 0; c < En / 32; c++) {
        __syncthreads();
        // fill 4 tiles
        {
            const size_t ge = (size_t)cr * En + c * 32;
            const int se = cr * GP;
#pragma unroll
            for (int j = 0; j < 2; j++) {
                int eo = (cj0 + j) * 8;
                *(uint4*)(Ahs + se + eo) = *(const uint4*)(Ahp + ge + eo);
                *(uint4*)(Als + se + eo) = *(const uint4*)(Alp + ge + eo);
                *(uint4*)(Bhs + se + eo) = *(const uint4*)(Bhp + ge + eo);
                *(uint4*)(Bls + se + eo) = *(const uint4*)(Blp + ge + eo);
            }
        }
        __syncthreads();

#pragma unroll
        for (int ks = 0; ks < 2; ks++) {
            const int kb = ks * 16;
            // A fragments: 2 m-frags x (hi, lo)
            uint32_t ah[2][4], al[2][4];
#pragma unroll
            for (int mf = 0; mf < 2; mf++) {
                uint32_t aaddr = smem_u32(Ahs + (wM + mf * 16 + arow) * GP + kb + akoff);
                ldsm_x4(ah[mf][0], ah[mf][1], ah[mf][2], ah[mf][3], aaddr);
                uint32_t aaddr2 = smem_u32(Als + (wM + mf * 16 + arow) * GP + kb + akoff);
                ldsm_x4(al[mf][0], al[mf][1], al[mf][2], al[mf][3], aaddr2);
            }
#pragma unroll
            for (int nf = 0; nf < 8; nf++) {
                uint32_t bh0, bh1, bl0, bl1;
                uint32_t baddr = smem_u32(Bhs + (wN + nf * 8 + blnr) * GP + kb + bkoff);
                ldsm_x2(bh0, bh1, baddr);
                uint32_t baddr2 = smem_u32(Bls + (wN + nf * 8 + blnr) * GP + kb + bkoff);
                ldsm_x2(bl0, bl1, baddr2);
#pragma unroll
                for (int mf = 0; mf < 2; mf++) {
                    mma_bf16(acc[mf][nf], ah[mf][0], ah[mf][1], ah[mf][2], ah[mf][3], bh0, bh1);
                    mma_bf16(acc[mf][nf], ah[mf][0], ah[mf][1], ah[mf][2], ah[mf][3], bl0, bl1);
                    mma_bf16(acc[mf][nf], al[mf][0], al[mf][1], al[mf][2], al[mf][3], bh0, bh1);
                }
            }
        }
    }

    // ---------------- epilogue ----------------
    const int mrow = lane >> 2;           // 0..7
    const int ncol = (lane & 3) * 2;      // 0,2,4,6

    if (mode == 0) {
        // n-band of 64 is head-aligned: head fixed per warp-n-band + nf
        const int nb = n0g + wN;          // 64-aligned
        const int which = nb >> 10;
        const float* bias = (which == 0) ? bias_q : (which == 1) ? bias_k : bias_v;
        float* dst = (which == 0) ? g_q : (which == 1) ? g_k : g_v;
        const int nl64 = nb & 1023;       // 64-aligned within 1024
        const int h = nl64 >> 6;
#pragma unroll
        for (int mf = 0; mf < 2; mf++) {
            int m = m0 + wM + mf * 16 + mrow;
            int bb = m >> 10, t = m & 1023;
            float* drow0 = dst + (((size_t)(bb * Hn + h)) * Tn + t) * Dn;
            float* drow1 = drow0 + 8 * Dn;   // m+8 -> t+8 (same b: m0 is 128-aligned, t%1024 safe)
#pragma unroll
            for (int nf = 0; nf < 8; nf++) {
                int d = (nl64 & 63) + nf * 8 + ncol;
                int nglob = nl64 + nf * 8 + ncol;
                float2 v0 = make_float2(acc[mf][nf][0] + bias[nglob],
                                        acc[mf][nf][1] + bias[nglob + 1]);
                float2 v1 = make_float2(acc[mf][nf][2] + bias[nglob],
                                        acc[mf][nf][3] + bias[nglob + 1]);
                *(float2*)(drow0 + d) = v0;
                *(float2*)(drow1 + d) = v1;
            }
        }
    } else {
        const float* bo = bias_q;
#pragma unroll
        for (int mf = 0; mf < 2; mf++) {
            int m = m0 + wM + mf * 16 + mrow;
            float* drow0 = out + (size_t)m * En;
            float* drow1 = drow0 + (size_t)8 * En;
#pragma unroll
            for (int nf = 0; nf < 8; nf++) {
                int n = n0g + wN + nf * 8 + ncol;
                float2 v0 = make_float2(acc[mf][nf][0] + bo[n], acc[mf][nf][1] + bo[n + 1]);
                float2 v1 = make_float2(acc[mf][nf][2] + bo[n], acc[mf][nf][3] + bo[n + 1]);
                *(float2*)(drow0 + n) = v0;
                *(float2*)(drow1 + n) = v1;
            }
        }
    }
}

// ---------------- flash attention, fp32, 128q x 128s tiles ----------------
#define BQ 128
#define BS 128
#define PSTR 132
#define SWZ(d) ((((d) >> 2) & 7) << 2)
#define ATTN_SMEM_FLOATS (8192 + 8192 + 8192 + 128*PSTR)
#define ATTN_SMEM_BYTES  (ATTN_SMEM_FLOATS * 4)

__global__ __launch_bounds__(256, 1) void attn_kernel(const float* __restrict__ noise)
{
    float* smf = (float*)dsm;
    float* QsT = smf;
    float* KsT = smf + 8192;
    float* Vs  = smf + 16384;
    float* Ps  = smf + 24576;

    const int tid = threadIdx.x;
    const int bh  = blockIdx.y;
    const int q0  = blockIdx.x * BQ;
    const int ty  = tid >> 4, tx = tid & 15;

    const float* Qg = g_q + ((size_t)bh * Tn + q0) * Dn;
    const float* Kg = g_k + (size_t)bh * Tn * Dn;
    const float* Vg = g_v + (size_t)bh * Tn * Dn;
    const float* Ng = noise + (size_t)bh * Tn * Tn + (size_t)q0 * Tn;

    const float Tm    = g_Tmean;
    const float scale = 0.125f;

    for (int idx = tid; idx < BQ * 16; idx += 256) {
        int r  = idx >> 4;
        int c4 = (idx & 15) << 2;
        int sw = SWZ(c4);
        float4 qv = *(const float4*)(Qg + (size_t)r * Dn + c4);
        QsT[(c4 + 0) * BQ + (r ^ sw)] = qv.x * scale;
        QsT[(c4 + 1) * BQ + (r ^ sw)] = qv.y * scale;
        QsT[(c4 + 2) * BQ + (r ^ sw)] = qv.z * scale;
        QsT[(c4 + 3) * BQ + (r ^ sw)] = qv.w * scale;
    }

    float m[8], l[8], acc[8][4];
#pragma unroll
    for (int i = 0; i < 8; i++) {
        m[i] = -1e30f; l[i] = 0.f;
        acc[i][0] = acc[i][1] = acc[i][2] = acc[i][3] = 0.f;
    }

    for (int st = 0; st < Tn; st += BS) {
        __syncthreads();
        for (int idx = tid; idx < BS * 16; idx += 256) {
            int r  = idx >> 4;
            int c4 = (idx & 15) << 2;
            int sw = SWZ(c4);
            float4 kv = *(const float4*)(Kg + (size_t)(st + r) * Dn + c4);
            KsT[(c4 + 0) * BS + (r ^ sw)] = kv.x;
            KsT[(c4 + 1) * BS + (r ^ sw)] = kv.y;
            KsT[(c4 + 2) * BS + (r ^ sw)] = kv.z;
            KsT[(c4 + 3) * BS + (r ^ sw)] = kv.w;
            float4 vv = *(const float4*)(Vg + (size_t)(st + r) * Dn + c4);
            *(float4*)&Vs[r * Dn + c4] = vv;
        }
        __syncthreads();

        float sreg[8][8];
#pragma unroll
        for (int i = 0; i < 8; i++)
#pragma unroll
            for (int j = 0; j < 8; j++) sreg[i][j] = 0.f;

#pragma unroll 4
        for (int d = 0; d < Dn; d++) {
            int sw = SWZ(d);
            const float* qrow = &QsT[d * BQ];
            const float* krow = &KsT[d * BS];
            float4 a0 = *(const float4*)(qrow + ((ty * 8) ^ sw));
            float4 a1 = *(const float4*)(qrow + (((ty * 8) ^ sw) ^ 4));
            float4 b0 = *(const float4*)(krow + ((tx * 8) ^ sw));
            float4 b1 = *(const float4*)(krow + (((tx * 8) ^ sw) ^ 4));
            float a[8] = {a0.x, a0.y, a0.z, a0.w, a1.x, a1.y, a1.z, a1.w};
            float b[8] = {b0.x, b0.y, b0.z, b0.w, b1.x, b1.y, b1.z, b1.w};
#pragma unroll
            for (int i = 0; i < 8; i++)
#pragma unroll
                for (int j = 0; j < 8; j++) sreg[i][j] += a[i] * b[j];
        }

#pragma unroll
        for (int i = 0; i < 8; i++) {
            float tmax = sreg[i][0];
#pragma unroll
            for (int j = 1; j < 8; j++) tmax = fmaxf(tmax, sreg[i][j]);
            tmax = fmaxf(tmax, __shfl_xor_sync(0xffffffffu, tmax, 1, 16));
            tmax = fmaxf(tmax, __shfl_xor_sync(0xffffffffu, tmax, 2, 16));
            tmax = fmaxf(tmax, __shfl_xor_sync(0xffffffffu, tmax, 4, 16));
            tmax = fmaxf(tmax, __shfl_xor_sync(0xffffffffu, tmax, 8, 16));
            float mn    = fmaxf(m[i], tmax);
            float alpha = __expf(m[i] - mn);
            m[i] = mn;
            float rs = 0.f;
#pragma unroll
            for (int j = 0; j < 8; j++) { sreg[i][j] = __expf(sreg[i][j] - mn); rs += sreg[i][j]; }
            rs += __shfl_xor_sync(0xffffffffu, rs, 1, 16);
            rs += __shfl_xor_sync(0xffffffffu, rs, 2, 16);
            rs += __shfl_xor_sync(0xffffffffu, rs, 4, 16);
            rs += __shfl_xor_sync(0xffffffffu, rs, 8, 16);
            l[i] = l[i] * alpha + rs;
            acc[i][0] *= alpha; acc[i][1] *= alpha; acc[i][2] *= alpha; acc[i][3] *= alpha;
        }

#pragma unroll
        for (int i = 0; i < 8; i++) {
            const float* nrow = Ng + (size_t)(ty * 8 + i) * Tn + st + tx * 8;
            float4 n0 = *(const float4*)nrow;
            float4 n1 = *(const float4*)(nrow + 4);
            float p0 = (n0.x > Tm) ? sreg[i][0] : 0.f;
            float p1 = (n0.y > Tm) ? sreg[i][1] : 0.f;
            float p2 = (n0.z > Tm) ? sreg[i][2] : 0.f;
            float p3 = (n0.w > Tm) ? sreg[i][3] : 0.f;
            float p4 = (n1.x > Tm) ? sreg[i][4] : 0.f;
            float p5 = (n1.y > Tm) ? sreg[i][5] : 0.f;
            float p6 = (n1.z > Tm) ? sreg[i][6] : 0.f;
            float p7 = (n1.w > Tm) ? sreg[i][7] : 0.f;
            *(float4*)&Ps[(ty * 8 + i) * PSTR + tx * 8]     = make_float4(p0, p1, p2, p3);
            *(float4*)&Ps[(ty * 8 + i) * PSTR + tx * 8 + 4] = make_float4(p4, p5, p6, p7);
        }
        __syncthreads();

#pragma unroll 2
        for (int ss = 0; ss < BS; ss++) {
            float4 bv = *(const float4*)&Vs[ss * Dn + tx * 4];
#pragma unroll
            for (int i = 0; i < 8; i++) {
                float a = Ps[(ty * 8 + i) * PSTR + ss];
                acc[i][0] += a * bv.x; acc[i][1] += a * bv.y;
                acc[i][2] += a * bv.z; acc[i][3] += a * bv.w;
            }
        }
    }

    // epilogue: write bf16 hi/lo split of output directly
    const float ks = g_keepScale;
    const int b = bh >> 4, h = bh & 15;
#pragma unroll
    for (int i = 0; i < 8; i++) {
        float inv = ks / l[i];
        int r = q0 + ty * 8 + i;
        float o0 = acc[i][0] * inv, o1 = acc[i][1] * inv;
        float o2 = acc[i][2] * inv, o3 = acc[i][3] * inv;
        __nv_bfloat16 h0 = __float2bfloat16(o0), h1 = __float2bfloat16(o1);
        __nv_bfloat16 h2 = __float2bfloat16(o2), h3 = __float2bfloat16(o3);
        __nv_bfloat16 l0 = __float2bfloat16(o0 - __bfloat162float(h0));
        __nv_bfloat16 l1 = __float2bfloat16(o1 - __bfloat162float(h1));
        __nv_bfloat16 l2 = __float2bfloat16(o2 - __bfloat162float(h2));
        __nv_bfloat16 l3 = __float2bfloat16(o3 - __bfloat162float(h3));
        size_t base = ((size_t)(b * Tn + r)) * En + h * Dn + tx * 4;
        ((__nv_bfloat162*)g_oh)[base / 2]     = __halves2bfloat162(h0, h1);
        ((__nv_bfloat162*)g_oh)[base / 2 + 1] = __halves2bfloat162(h2, h3);
        ((__nv_bfloat162*)g_ol)[base / 2]     = __halves2bfloat162(l0, l1);
        ((__nv_bfloat162*)g_ol)[base / 2 + 1] = __halves2bfloat162(l2, l3);
    }
}

// ---------------- launch ----------------
extern "C" void kernel_launch(void* const* d_in, const int* in_sizes, int n_in,
                              void* d_out, int out_size)
{
    const float* x     = (const float*)d_in[0];
    const float* noise = (const float*)d_in[1];
    const float* Wq    = (const float*)d_in[2];
    const float* bq    = (const float*)d_in[3];
    const float* Wk    = (const float*)d_in[4];
    const float* bk    = (const float*)d_in[5];
    const float* Wv    = (const float*)d_in[6];
    const float* bv    = (const float*)d_in[7];
    const float* Wo    = (const float*)d_in[8];
    const float* bo    = (const float*)d_in[9];
    const float* theta = (const float*)d_in[10];
    float* out = (float*)d_out;

    cudaFuncSetAttribute(attn_kernel, cudaFuncAttributeMaxDynamicSharedMemorySize,
                         ATTN_SMEM_BYTES);
    cudaFuncSetAttribute(hmma_linear_kernel, cudaFuncAttributeMaxDynamicSharedMemorySize,
                         GEMM_SMEM_BYTES);

    prep_kernel<<<1, 32>>>(theta);

    // split conversions: x and the four weight matrices (packed rows in g_wh/g_wl)
    conv_kernel<<<(Mn * En / 4 + 255) / 256, 256>>>(x, 0, 0, Mn * En / 4);
    conv_kernel<<<(En * En / 4 + 255) / 256, 256>>>(Wq, 1, (size_t)0 * En * En, En * En / 4);
    conv_kernel<<<(En * En / 4 + 255) / 256, 256>>>(Wk, 1, (size_t)1 * En * En, En * En / 4);
    conv_kernel<<<(En * En / 4 + 255) / 256, 256>>>(Wv, 1, (size_t)2 * En * En, En * En / 4);
    conv_kernel<<<(En * En / 4 + 255) / 256, 256>>>(Wo, 1, (size_t)3 * En * En, En * En / 4);

    // QKV projection on HMMA tensor cores (N over [Wq|Wk|Wv] = 3072)
    hmma_linear_kernel<<<dim3(24, 32), 256, GEMM_SMEM_BYTES>>>(
        0, 0, bq, bk, bv, nullptr, 0);

    attn_kernel<<<dim3(Tn / BQ, BHn), 256, ATTN_SMEM_BYTES>>>(noise);

    // output projection (B rows 3072..4095 = Wo)
    hmma_linear_kernel<<<dim3(8, 32), 256, GEMM_SMEM_BYTES>>>(
        1, 3072, bo, nullptr, nullptr, out, 1);
}